// round 11
// baseline (speedup 1.0000x reference)
#include <cuda_runtime.h>
#include <cuda_fp16.h>
#include <math.h>

#define NBATCH 8
#define LSEQ   2048
#define CDIM   256
#define DDIM   32
#define MROWS  (NBATCH * LSEQ)   // 16384
#define NTILES (LSEQ / 64)       // 32 key tiles

// ---------------------------------------------------------------------------
// Device scratch
// ---------------------------------------------------------------------------
__device__ float  g_ecg[MROWS * CDIM];
__device__ float  g_pcg[MROWS * CDIM];
__device__ float  g_QK[4][MROWS * 64];       // fused [Q|K] fp32 (Q half valid)
__device__ __half g_Khi[4][MROWS * 32];      // K hi fp16, row stride 32
__device__ __half g_Klo[4][MROWS * 32];      // K lo fp16
__device__ __half g_Vh[4][MROWS * CDIM];     // V scratch fp16

// ---------------------------------------------------------------------------
// Helpers
// ---------------------------------------------------------------------------
__device__ __forceinline__ unsigned cvt_tf32(float f) {
    unsigned u; asm("cvt.rna.tf32.f32 %0, %1;" : "=r"(u) : "f"(f)); return u;
}
__device__ __forceinline__ float cvt_tf32f(float f) {
    return __uint_as_float(cvt_tf32(f));
}
__device__ __forceinline__ unsigned fasu(float f) { return __float_as_uint(f); }

__device__ __forceinline__ void mma_tf32(float* c,
                                         unsigned a0, unsigned a1, unsigned a2, unsigned a3,
                                         unsigned b0, unsigned b1) {
    asm volatile("mma.sync.aligned.m16n8k8.row.col.f32.tf32.tf32.f32 "
                 "{%0,%1,%2,%3}, {%4,%5,%6,%7}, {%8,%9}, {%0,%1,%2,%3};"
                 : "+f"(c[0]), "+f"(c[1]), "+f"(c[2]), "+f"(c[3])
                 : "r"(a0), "r"(a1), "r"(a2), "r"(a3), "r"(b0), "r"(b1));
}

__device__ __forceinline__ void mma16(float* c, const unsigned* a,
                                      unsigned b0, unsigned b1) {
    asm volatile("mma.sync.aligned.m16n8k16.row.col.f32.f16.f16.f32 "
                 "{%0,%1,%2,%3}, {%4,%5,%6,%7}, {%8,%9}, {%0,%1,%2,%3};"
                 : "+f"(c[0]), "+f"(c[1]), "+f"(c[2]), "+f"(c[3])
                 : "r"(a[0]), "r"(a[1]), "r"(a[2]), "r"(a[3]), "r"(b0), "r"(b1));
}

__device__ __forceinline__ unsigned h2u(__half2 h) { return *reinterpret_cast<unsigned*>(&h); }

__device__ __forceinline__ void split2(float x, float y, unsigned& hi, unsigned& lo) {
    __half2 h = __floats2half2_rn(x, y);
    float2 hf = __half22float2(h);
    __half2 l = __floats2half2_rn(x - hf.x, y - hf.y);
    hi = h2u(h); lo = h2u(l);
}

__device__ __forceinline__ unsigned su(const void* p) {
    return (unsigned)__cvta_generic_to_shared(p);
}
#define CP16(dst, src) \
    asm volatile("cp.async.cg.shared.global [%0], [%1], 16;" :: "r"(dst), "l"(src))
#define CP_COMMIT() asm volatile("cp.async.commit_group;")

#define LDSM_X4(r0, r1, r2, r3, addr) \
    asm volatile("ldmatrix.sync.aligned.m8n8.x4.shared.b16 {%0,%1,%2,%3}, [%4];" \
                 : "=r"(r0), "=r"(r1), "=r"(r2), "=r"(r3) : "r"(addr))
#define LDSM_X4T(r0, r1, r2, r3, addr) \
    asm volatile("ldmatrix.sync.aligned.m8n8.x4.trans.shared.b16 {%0,%1,%2,%3}, [%4];" \
                 : "=r"(r0), "=r"(r1), "=r"(r2), "=r"(r3) : "r"(addr))

// ---------------------------------------------------------------------------
// Split x[B,L,C,2] into two streams
// ---------------------------------------------------------------------------
__global__ void split_kernel(const float2* __restrict__ x,
                             float* __restrict__ e, float* __restrict__ p) {
    int i = blockIdx.x * blockDim.x + threadIdx.x;
    if (i < MROWS * CDIM) {
        float2 v = x[i];
        e[i] = v.x;
        p[i] = v.y;
    }
}

// ---------------------------------------------------------------------------
// Fused QK projection, split-tf32 (3-mma), z-indexed args.
// ---------------------------------------------------------------------------
struct QkArgs {
    const float* X[2]; const float* Wa[2]; const float* Wb[2];
    float* Y[2]; __half* Khi[2]; __half* Klo[2]; int khalf[2];
    const float* gate[2];
};

__global__ __launch_bounds__(256)
void proj_qk3(QkArgs a) {
    const int z = blockIdx.z;
    const float* gate = a.gate[z];
    if (gate && gate[0] == 0.0f) return;
    const float* X  = a.X[z];
    const float* Wa = a.Wa[z];
    const float* Wb = a.Wb[z];
    float* Y = a.Y[z];
    __half* Khi = a.Khi[z];
    __half* Klo = a.Klo[z];
    const int khalf = a.khalf[z];

    __shared__ float Xh[128][36], Xl[128][36];
    __shared__ float Wh[32][72], Wl[32][72];

    const int tid = threadIdx.x, w = tid >> 5, lane = tid & 31;
    const int qr = lane >> 2, qc = lane & 3;
    const int m0 = blockIdx.y * 128;

    float acc[8][4];
#pragma unroll
    for (int nt = 0; nt < 8; nt++)
        acc[nt][0] = acc[nt][1] = acc[nt][2] = acc[nt][3] = 0.0f;

    for (int k0 = 0; k0 < CDIM; k0 += 32) {
#pragma unroll
        for (int t = 0; t < 16; t++) {
            int e = tid + t * 256; int r = e >> 5, c = e & 31;
            float f = X[(size_t)(m0 + r) * CDIM + k0 + c];
            float h = cvt_tf32f(f);
            Xh[r][c] = h; Xl[r][c] = cvt_tf32f(f - h);
        }
#pragma unroll
        for (int t = 0; t < 8; t++) {
            int e = tid + t * 256; int r = e >> 6, c = e & 63;
            float f = (c < 32) ? Wa[(size_t)(k0 + r) * DDIM + c]
                               : Wb[(size_t)(k0 + r) * DDIM + (c - 32)];
            float h = cvt_tf32f(f);
            Wh[r][c] = h; Wl[r][c] = cvt_tf32f(f - h);
        }
        __syncthreads();

        const int r = w * 16 + qr;
#pragma unroll
        for (int kt = 0; kt < 4; kt++) {
            unsigned ah0 = fasu(Xh[r][kt * 8 + qc]);
            unsigned ah1 = fasu(Xh[r + 8][kt * 8 + qc]);
            unsigned ah2 = fasu(Xh[r][kt * 8 + qc + 4]);
            unsigned ah3 = fasu(Xh[r + 8][kt * 8 + qc + 4]);
            unsigned al0 = fasu(Xl[r][kt * 8 + qc]);
            unsigned al1 = fasu(Xl[r + 8][kt * 8 + qc]);
            unsigned al2 = fasu(Xl[r][kt * 8 + qc + 4]);
            unsigned al3 = fasu(Xl[r + 8][kt * 8 + qc + 4]);
#pragma unroll
            for (int nt = 0; nt < 8; nt++) {
                unsigned bh0 = fasu(Wh[kt * 8 + qc][nt * 8 + qr]);
                unsigned bh1 = fasu(Wh[kt * 8 + qc + 4][nt * 8 + qr]);
                unsigned bl0 = fasu(Wl[kt * 8 + qc][nt * 8 + qr]);
                unsigned bl1 = fasu(Wl[kt * 8 + qc + 4][nt * 8 + qr]);
                mma_tf32(acc[nt], ah0, ah1, ah2, ah3, bh0, bh1);
                mma_tf32(acc[nt], al0, al1, al2, al3, bh0, bh1);
                mma_tf32(acc[nt], ah0, ah1, ah2, ah3, bl0, bl1);
            }
        }
        __syncthreads();
    }

    const int r = m0 + w * 16 + qr;
#pragma unroll
    for (int nt = 0; nt < 8; nt++) {
        if ((nt >> 2) != khalf) {
            int c = nt * 8 + 2 * qc;
            *(float2*)&Y[(size_t)r * 64 + c]       = make_float2(acc[nt][0], acc[nt][1]);
            *(float2*)&Y[(size_t)(r + 8) * 64 + c] = make_float2(acc[nt][2], acc[nt][3]);
        } else {
            int c = (nt - 4 * khalf) * 8 + 2 * qc;
            unsigned hi0, lo0, hi1, lo1;
            split2(acc[nt][0], acc[nt][1], hi0, lo0);
            split2(acc[nt][2], acc[nt][3], hi1, lo1);
            *(unsigned*)&Khi[(size_t)r * 32 + c]       = hi0;
            *(unsigned*)&Klo[(size_t)r * 32 + c]       = lo0;
            *(unsigned*)&Khi[(size_t)(r + 8) * 32 + c] = hi1;
            *(unsigned*)&Klo[(size_t)(r + 8) * 32 + c] = lo1;
        }
    }
}

// ---------------------------------------------------------------------------
// V projection: R2's measured tf32 proj_mma<64> body (38.8us, issue 66%),
// only change: fp16 output + z-indexed args.
// ---------------------------------------------------------------------------
struct PvArgs {
    const float* X[2]; const float* W[2]; __half* Y[2]; const float* gate[2];
};

__global__ __launch_bounds__(256)
void proj_v(PvArgs a) {
    const int z = blockIdx.z;
    const float* gate = a.gate[z];
    if (gate && gate[0] == 0.0f) return;
    const float* X = a.X[z];
    const float* W = a.W[z];
    __half* Y = a.Y[z];

    __shared__ float Xs[128][36];        // pitch 36 -> conflict-free A-frag reads
    __shared__ float Ws[32][72];         // pitch % 32 == 8 -> conflict-free B-frag reads

    const int tid = threadIdx.x, w = tid >> 5, lane = tid & 31;
    const int qr = lane >> 2, qc = lane & 3;
    const int m0 = blockIdx.y * 128, n0 = blockIdx.x * 64;

    float acc[8][4];
#pragma unroll
    for (int nt = 0; nt < 8; nt++)
        acc[nt][0] = acc[nt][1] = acc[nt][2] = acc[nt][3] = 0.0f;

    for (int k0 = 0; k0 < CDIM; k0 += 32) {
#pragma unroll
        for (int t = 0; t < 16; t++) {
            int e = tid + t * 256; int r = e >> 5, c = e & 31;
            Xs[r][c] = cvt_tf32f(X[(size_t)(m0 + r) * CDIM + k0 + c]);
        }
#pragma unroll
        for (int t = 0; t < 8; t++) {
            int e = tid + t * 256; int r = e >> 6, c = e & 63;
            Ws[r][c] = cvt_tf32f(W[(size_t)(k0 + r) * CDIM + n0 + c]);
        }
        __syncthreads();

        const int r = w * 16 + qr;
#pragma unroll
        for (int kt = 0; kt < 4; kt++) {
            unsigned a0 = fasu(Xs[r][kt * 8 + qc]);
            unsigned a1 = fasu(Xs[r + 8][kt * 8 + qc]);
            unsigned a2 = fasu(Xs[r][kt * 8 + qc + 4]);
            unsigned a3 = fasu(Xs[r + 8][kt * 8 + qc + 4]);
#pragma unroll
            for (int nt = 0; nt < 8; nt++) {
                unsigned b0 = fasu(Ws[kt * 8 + qc][nt * 8 + qr]);
                unsigned b1 = fasu(Ws[kt * 8 + qc + 4][nt * 8 + qr]);
                mma_tf32(acc[nt], a0, a1, a2, a3, b0, b1);
            }
        }
        __syncthreads();
    }

    const int r = m0 + w * 16 + qr;
#pragma unroll
    for (int nt = 0; nt < 8; nt++) {
        int c = n0 + nt * 8 + 2 * qc;
        *(__half2*)&Y[(size_t)r * CDIM + c]       = __floats2half2_rn(acc[nt][0], acc[nt][1]);
        *(__half2*)&Y[(size_t)(r + 8) * CDIM + c] = __floats2half2_rn(acc[nt][2], acc[nt][3]);
    }
}

// ---------------------------------------------------------------------------
// Flash attention: R8's measured 256-thread body (8 warps = 4 row-groups x
// 2 col-groups, 2 blocks/SM), z-indexed args.
// ---------------------------------------------------------------------------
struct AttnArgs {
    const float*  Q[2];
    const __half* Khi[2];
    const __half* Klo[2];
    const __half* V[2];
    const float*  gate[2];
    int chan0[2];
    int addMode;
};

struct ASmem {
    __half Khi[2][64][40];    // 80B pitch, conflict-free ldmatrix
    __half Klo[2][64][40];
    __half Vs[2][64][264];    // 528B pitch, conflict-free ldmatrix.trans
};
extern __shared__ char attn_raw[];

__global__ __launch_bounds__(256, 2)
void attn16(AttnArgs args, float* __restrict__ out) {
    const int z = blockIdx.z;
    const float* gate = args.gate[z];
    if (gate && gate[0] == 0.0f) return;
    const float gv = gate ? gate[0] : 1.0f;

    ASmem* S = reinterpret_cast<ASmem*>(attn_raw);
    const int tid = threadIdx.x, w = tid >> 5, lane = tid & 31;
    const int qr = lane >> 2, qc = lane & 3;
    const int wr = w >> 1, wc = w & 1;
    const int qt = blockIdx.x, b = blockIdx.y;
    const int r0 = wr * 16 + qr;
    const int c0 = wc * 128;

    const size_t rowbase = (size_t)b * LSEQ + (size_t)qt * 64;
    const float*  Qp  = args.Q[z]   + rowbase * 64;
    const __half* Khp = args.Khi[z] + (size_t)b * LSEQ * 32;
    const __half* Klp = args.Klo[z] + (size_t)b * LSEQ * 32;
    const __half* Vp  = args.V[z]   + (size_t)b * LSEQ * CDIM;
    const float isc = rsqrtf((float)DDIM);

    // Q fragments fp32 -> hi/lo fp16
    unsigned qh[2][4], ql[2][4];
#pragma unroll
    for (int kt = 0; kt < 2; kt++) {
        float2 fa = *(const float2*)&Qp[(size_t)r0 * 64 + kt * 16 + 2 * qc];
        float2 fb = *(const float2*)&Qp[(size_t)(r0 + 8) * 64 + kt * 16 + 2 * qc];
        float2 fc = *(const float2*)&Qp[(size_t)r0 * 64 + kt * 16 + 2 * qc + 8];
        float2 fd = *(const float2*)&Qp[(size_t)(r0 + 8) * 64 + kt * 16 + 2 * qc + 8];
        split2(fa.x * isc, fa.y * isc, qh[kt][0], ql[kt][0]);
        split2(fb.x * isc, fb.y * isc, qh[kt][1], ql[kt][1]);
        split2(fc.x * isc, fc.y * isc, qh[kt][2], ql[kt][2]);
        split2(fd.x * isc, fd.y * isc, qh[kt][3], ql[kt][3]);
    }

    float acc[16][4];
#pragma unroll
    for (int nt = 0; nt < 16; nt++)
        acc[nt][0] = acc[nt][1] = acc[nt][2] = acc[nt][3] = 0.0f;
    float m0v = -3.402823466e38f, m1v = -3.402823466e38f, l0 = 0.0f, l1 = 0.0f;

    auto issue = [&](int t) {
        int bufi = t & 1;
        int j0 = t * 64;
        const __half* Vg = Vp + (size_t)j0 * CDIM;
#pragma unroll
        for (int i = 0; i < 8; i++) {
            int e = tid + i * 256; int key = e >> 5, c = e & 31;
            CP16(su(&S->Vs[bufi][key][c * 8]), Vg + (size_t)key * CDIM + c * 8);
        }
#pragma unroll
        for (int i = 0; i < 2; i++) {
            int e = tid + i * 256; int key = e >> 3, c = e & 7;
            if (c < 4)
                CP16(su(&S->Khi[bufi][key][c * 8]),
                     Khp + (size_t)(j0 + key) * 32 + c * 8);
            else
                CP16(su(&S->Klo[bufi][key][(c - 4) * 8]),
                     Klp + (size_t)(j0 + key) * 32 + (c - 4) * 8);
        }
        CP_COMMIT();
    };

    issue(0);
    issue(1);

    for (int t = 0; t < NTILES; t++) {
        const int bufi = t & 1;
        if (t + 1 < NTILES) asm volatile("cp.async.wait_group 1;");
        else                asm volatile("cp.async.wait_group 0;");
        __syncthreads();

        // ---- S = Q K^T, split-fp16 3-mma; K frags via ldmatrix.x4
        float sf[8][4];
#pragma unroll
        for (int nt = 0; nt < 8; nt++)
            sf[nt][0] = sf[nt][1] = sf[nt][2] = sf[nt][3] = 0.0f;
#pragma unroll
        for (int kt = 0; kt < 2; kt++) {
#pragma unroll
            for (int ng = 0; ng < 4; ng++) {
                int krow = ng * 16 + (lane & 7) + ((lane >> 4) << 3);
                int dcol = kt * 16 + ((lane >> 3) & 1) * 8;
                unsigned bh0, bh1, bh2, bh3, bl0, bl1, bl2, bl3;
                LDSM_X4(bh0, bh1, bh2, bh3, su(&S->Khi[bufi][krow][dcol]));
                LDSM_X4(bl0, bl1, bl2, bl3, su(&S->Klo[bufi][krow][dcol]));
                mma16(sf[2 * ng],     qh[kt], bh0, bh1);
                mma16(sf[2 * ng],     ql[kt], bh0, bh1);
                mma16(sf[2 * ng],     qh[kt], bl0, bl1);
                mma16(sf[2 * ng + 1], qh[kt], bh2, bh3);
                mma16(sf[2 * ng + 1], ql[kt], bh2, bh3);
                mma16(sf[2 * ng + 1], qh[kt], bl2, bl3);
            }
        }

        // ---- online softmax (registers + quad shuffles)
        float rm0 = -3.402823466e38f, rm1 = -3.402823466e38f;
#pragma unroll
        for (int nt = 0; nt < 8; nt++) {
            rm0 = fmaxf(rm0, fmaxf(sf[nt][0], sf[nt][1]));
            rm1 = fmaxf(rm1, fmaxf(sf[nt][2], sf[nt][3]));
        }
        rm0 = fmaxf(rm0, __shfl_xor_sync(0xffffffffu, rm0, 1));
        rm0 = fmaxf(rm0, __shfl_xor_sync(0xffffffffu, rm0, 2));
        rm1 = fmaxf(rm1, __shfl_xor_sync(0xffffffffu, rm1, 1));
        rm1 = fmaxf(rm1, __shfl_xor_sync(0xffffffffu, rm1, 2));
        float nm0 = fmaxf(m0v, rm0), nm1 = fmaxf(m1v, rm1);
        float sc0 = __expf(m0v - nm0), sc1 = __expf(m1v - nm1);
        float rs0 = 0.0f, rs1 = 0.0f;
#pragma unroll
        for (int nt = 0; nt < 8; nt++) {
            sf[nt][0] = __expf(sf[nt][0] - nm0); sf[nt][1] = __expf(sf[nt][1] - nm0);
            sf[nt][2] = __expf(sf[nt][2] - nm1); sf[nt][3] = __expf(sf[nt][3] - nm1);
            rs0 += sf[nt][0] + sf[nt][1];
            rs1 += sf[nt][2] + sf[nt][3];
        }
        rs0 += __shfl_xor_sync(0xffffffffu, rs0, 1);
        rs0 += __shfl_xor_sync(0xffffffffu, rs0, 2);
        rs1 += __shfl_xor_sync(0xffffffffu, rs1, 1);
        rs1 += __shfl_xor_sync(0xffffffffu, rs1, 2);
        l0 = l0 * sc0 + rs0; l1 = l1 * sc1 + rs1;
        m0v = nm0; m1v = nm1;
        if (sc0 != 1.0f || sc1 != 1.0f) {
#pragma unroll
            for (int nt = 0; nt < 16; nt++) {
                acc[nt][0] *= sc0; acc[nt][1] *= sc0;
                acc[nt][2] *= sc1; acc[nt][3] *= sc1;
            }
        }

        // ---- pack P into A-fragments (S-frag layout == A-frag layout)
        unsigned pa[4][4];
#pragma unroll
        for (int kt = 0; kt < 4; kt++) {
            pa[kt][0] = h2u(__floats2half2_rn(sf[2 * kt][0],     sf[2 * kt][1]));
            pa[kt][1] = h2u(__floats2half2_rn(sf[2 * kt][2],     sf[2 * kt][3]));
            pa[kt][2] = h2u(__floats2half2_rn(sf[2 * kt + 1][0], sf[2 * kt + 1][1]));
            pa[kt][3] = h2u(__floats2half2_rn(sf[2 * kt + 1][2], sf[2 * kt + 1][3]));
        }

        // ---- acc += P V  (ldmatrix.x4.trans for V B-fragments)
#pragma unroll
        for (int kt = 0; kt < 4; kt++) {
#pragma unroll
            for (int np = 0; np < 8; np++) {
                unsigned b0, b1, b2, b3;
                unsigned addr = su(&S->Vs[bufi][kt * 16 + (lane & 15)]
                                         [c0 + np * 16 + (lane >> 4) * 8]);
                LDSM_X4T(b0, b1, b2, b3, addr);
                mma16(acc[2 * np],     pa[kt], b0, b1);
                mma16(acc[2 * np + 1], pa[kt], b2, b3);
            }
        }

        __syncthreads();
        if (t + 2 < NTILES) issue(t + 2);
    }

    // ---- epilogue
    float il0 = 1.0f / l0, il1 = 1.0f / l1;
    float* o0 = out + (rowbase + r0) * (2 * CDIM) + args.chan0[z] + c0;
    float* o1 = o0 + (size_t)8 * (2 * CDIM);
    if (args.addMode) {
#pragma unroll
        for (int nt = 0; nt < 16; nt++) {
            int c = nt * 8 + 2 * qc;
            o0[c]     += gv * acc[nt][0] * il0;
            o0[c + 1] += gv * acc[nt][1] * il0;
            o1[c]     += gv * acc[nt][2] * il1;
            o1[c + 1] += gv * acc[nt][3] * il1;
        }
    } else {
#pragma unroll
        for (int nt = 0; nt < 16; nt++) {
            int c = nt * 8 + 2 * qc;
            *(float2*)&o0[c] = make_float2(acc[nt][0] * il0, acc[nt][1] * il0);
            *(float2*)&o1[c] = make_float2(acc[nt][2] * il1, acc[nt][3] * il1);
        }
    }
}

// ---------------------------------------------------------------------------
// Launcher.  attn_main at launch index 4 (5th kernel) for the profiler slot.
// ---------------------------------------------------------------------------
extern "C" void kernel_launch(void* const* d_in, const int* in_sizes, int n_in,
                              void* d_out, int out_size) {
    const float* x = (const float*)d_in[0];
    const float* w[13];
    for (int i = 1; i <= 12; i++) w[i] = (const float*)d_in[i];
    const float* alpha = (const float*)d_in[13];
    const float* gamma = (const float*)d_in[14];
    float* out = (float*)d_out;

    float *ecg, *pcg, *qk; __half *vh, *khi, *klo;
    cudaGetSymbolAddress((void**)&ecg, g_ecg);
    cudaGetSymbolAddress((void**)&pcg, g_pcg);
    cudaGetSymbolAddress((void**)&qk,  g_QK);
    cudaGetSymbolAddress((void**)&vh,  g_Vh);
    cudaGetSymbolAddress((void**)&khi, g_Khi);
    cudaGetSymbolAddress((void**)&klo, g_Klo);

    auto QK = [&](int a) { return qk  + (size_t)a * MROWS * 64; };
    auto KH = [&](int a) { return khi + (size_t)a * MROWS * 32; };
    auto KL = [&](int a) { return klo + (size_t)a * MROWS * 32; };
    auto VH = [&](int a) { return vh  + (size_t)a * MROWS * CDIM; };

    cudaFuncSetAttribute(attn16, cudaFuncAttributeMaxDynamicSharedMemorySize,
                         (int)sizeof(ASmem));

    // (0) de-interleave
    split_kernel<<<(MROWS * CDIM + 255) / 256, 256>>>((const float2*)x, ecg, pcg);

    dim3 gQ(1, MROWS / 128, 2);
    dim3 gV(CDIM / 64, MROWS / 128, 2);
    dim3 gA(LSEQ / 64, NBATCH, 2);
    size_t smem = sizeof(ASmem);

    // (1) ungated QK projections: z=0 -> [Q0|K1], z=1 -> [K0|Q1]
    QkArgs qm{};
    qm.X[0] = ecg; qm.Wa[0] = w[4]; qm.Wb[0] = w[11];
    qm.Y[0] = QK(0); qm.Khi[0] = KH(1); qm.Klo[0] = KL(1); qm.khalf[0] = 1;
    qm.X[1] = pcg; qm.Wa[1] = w[5]; qm.Wb[1] = w[10];
    qm.Y[1] = QK(1); qm.Khi[1] = KH(0); qm.Klo[1] = KL(0); qm.khalf[1] = 0;
    proj_qk3<<<gQ, 256>>>(qm);

    // (2) gated QK projections: z=0 alpha [Q2|K2], z=1 gamma [Q3|K3]
    QkArgs qg{};
    qg.X[0] = ecg; qg.Wa[0] = w[1]; qg.Wb[0] = w[2];
    qg.Y[0] = QK(2); qg.Khi[0] = KH(2); qg.Klo[0] = KL(2); qg.khalf[0] = 1;
    qg.gate[0] = alpha;
    qg.X[1] = pcg; qg.Wa[1] = w[7]; qg.Wb[1] = w[8];
    qg.Y[1] = QK(3); qg.Khi[1] = KH(3); qg.Klo[1] = KL(3); qg.khalf[1] = 1;
    qg.gate[1] = gamma;
    proj_qk3<<<gQ, 256>>>(qg);

    // (3) ungated V projections
    PvArgs pm{};
    pm.X[0] = pcg; pm.W[0] = w[6];  pm.Y[0] = VH(0);
    pm.X[1] = ecg; pm.W[1] = w[12]; pm.Y[1] = VH(1);
    proj_v<<<gV, 256>>>(pm);

    // (4) MAIN ATTENTION: z=0 ecg_inter, z=1 pcg_inter
    AttnArgs am{};
    am.Q[0] = QK(0);      am.Khi[0] = KH(0); am.Klo[0] = KL(0); am.V[0] = VH(0);
    am.Q[1] = QK(1) + 32; am.Khi[1] = KH(1); am.Klo[1] = KL(1); am.V[1] = VH(1);
    am.chan0[0] = 0; am.chan0[1] = CDIM;
    am.addMode = 0;
    attn16<<<gA, 256, smem>>>(am, out);

    // (5) gated V projections
    PvArgs pg{};
    pg.X[0] = ecg; pg.W[0] = w[3]; pg.Y[0] = VH(2); pg.gate[0] = alpha;
    pg.X[1] = pcg; pg.W[1] = w[9]; pg.Y[1] = VH(3); pg.gate[1] = gamma;
    proj_v<<<gV, 256>>>(pg);

    // (6) gated intra attentions (+= after main's =)
    AttnArgs ag{};
    ag.Q[0] = QK(2); ag.Khi[0] = KH(2); ag.Klo[0] = KL(2); ag.V[0] = VH(2);
    ag.Q[1] = QK(3); ag.Khi[1] = KH(3); ag.Klo[1] = KL(3); ag.V[1] = VH(3);
    ag.gate[0] = alpha; ag.gate[1] = gamma;
    ag.chan0[0] = 0; ag.chan0[1] = CDIM;
    ag.addMode = 1;
    attn16<<<gA, 256, smem>>>(ag, out);
}

// round 14
// speedup vs baseline: 1.3777x; 1.3777x over previous
#include <cuda_runtime.h>
#include <cuda_fp16.h>
#include <math.h>

#define NBATCH 8
#define LSEQ   2048
#define CDIM   256
#define DDIM   32
#define MROWS  (NBATCH * LSEQ)   // 16384
#define NTILES (LSEQ / 64)       // 32 key tiles

// ---------------------------------------------------------------------------
// Device scratch
// ---------------------------------------------------------------------------
__device__ float  g_ecg[MROWS * CDIM];
__device__ float  g_pcg[MROWS * CDIM];
__device__ float  g_QK[4][MROWS * 64];       // fused [Q|K] fp32 (Q half valid)
__device__ __half g_Khi[4][MROWS * 32];      // K hi fp16, row stride 32
__device__ __half g_Klo[4][MROWS * 32];      // K lo fp16
__device__ __half g_Vh[4][MROWS * CDIM];     // V scratch fp16

// ---------------------------------------------------------------------------
// Helpers
// ---------------------------------------------------------------------------
__device__ __forceinline__ unsigned cvt_tf32(float f) {
    unsigned u; asm("cvt.rna.tf32.f32 %0, %1;" : "=r"(u) : "f"(f)); return u;
}
__device__ __forceinline__ float cvt_tf32f(float f) {
    return __uint_as_float(cvt_tf32(f));
}
__device__ __forceinline__ unsigned fasu(float f) { return __float_as_uint(f); }

__device__ __forceinline__ void mma_tf32(float* c,
                                         unsigned a0, unsigned a1, unsigned a2, unsigned a3,
                                         unsigned b0, unsigned b1) {
    asm volatile("mma.sync.aligned.m16n8k8.row.col.f32.tf32.tf32.f32 "
                 "{%0,%1,%2,%3}, {%4,%5,%6,%7}, {%8,%9}, {%0,%1,%2,%3};"
                 : "+f"(c[0]), "+f"(c[1]), "+f"(c[2]), "+f"(c[3])
                 : "r"(a0), "r"(a1), "r"(a2), "r"(a3), "r"(b0), "r"(b1));
}

__device__ __forceinline__ void mma16(float* c, const unsigned* a,
                                      unsigned b0, unsigned b1) {
    asm volatile("mma.sync.aligned.m16n8k16.row.col.f32.f16.f16.f32 "
                 "{%0,%1,%2,%3}, {%4,%5,%6,%7}, {%8,%9}, {%0,%1,%2,%3};"
                 : "+f"(c[0]), "+f"(c[1]), "+f"(c[2]), "+f"(c[3])
                 : "r"(a[0]), "r"(a[1]), "r"(a[2]), "r"(a[3]), "r"(b0), "r"(b1));
}

__device__ __forceinline__ unsigned h2u(__half2 h) { return *reinterpret_cast<unsigned*>(&h); }

__device__ __forceinline__ void split2(float x, float y, unsigned& hi, unsigned& lo) {
    __half2 h = __floats2half2_rn(x, y);
    float2 hf = __half22float2(h);
    __half2 l = __floats2half2_rn(x - hf.x, y - hf.y);
    hi = h2u(h); lo = h2u(l);
}

__device__ __forceinline__ unsigned su(const void* p) {
    return (unsigned)__cvta_generic_to_shared(p);
}
#define CP16(dst, src) \
    asm volatile("cp.async.cg.shared.global [%0], [%1], 16;" :: "r"(dst), "l"(src))
#define CP_COMMIT() asm volatile("cp.async.commit_group;")

#define LDSM_X4(r0, r1, r2, r3, addr) \
    asm volatile("ldmatrix.sync.aligned.m8n8.x4.shared.b16 {%0,%1,%2,%3}, [%4];" \
                 : "=r"(r0), "=r"(r1), "=r"(r2), "=r"(r3) : "r"(addr))
#define LDSM_X4T(r0, r1, r2, r3, addr) \
    asm volatile("ldmatrix.sync.aligned.m8n8.x4.trans.shared.b16 {%0,%1,%2,%3}, [%4];" \
                 : "=r"(r0), "=r"(r1), "=r"(r2), "=r"(r3) : "r"(addr))

// ---------------------------------------------------------------------------
// Split x[B,L,C,2] into two streams
// ---------------------------------------------------------------------------
__global__ void split_kernel(const float2* __restrict__ x,
                             float* __restrict__ e, float* __restrict__ p) {
    int i = blockIdx.x * blockDim.x + threadIdx.x;
    if (i < MROWS * CDIM) {
        float2 v = x[i];
        e[i] = v.x;
        p[i] = v.y;
    }
}

// ---------------------------------------------------------------------------
// Fused QK projection, split-tf32 (3-mma) for ~fp32 accuracy.
// Y[M][64] = X @ [Wa | Wb].  Q half written fp32 into Y; K half (selected by
// khalf) written as fp16 hi/lo into Khi/Klo (row stride 32).
// ---------------------------------------------------------------------------
__global__ __launch_bounds__(256)
void proj_qk3(const float* __restrict__ X,
              const float* __restrict__ Wa, const float* __restrict__ Wb,
              float* __restrict__ Y,
              __half* __restrict__ Khi, __half* __restrict__ Klo, int khalf,
              const float* __restrict__ gate) {
    if (gate && gate[0] == 0.0f) return;

    __shared__ float Xh[128][36], Xl[128][36];
    __shared__ float Wh[32][72], Wl[32][72];

    const int tid = threadIdx.x, w = tid >> 5, lane = tid & 31;
    const int qr = lane >> 2, qc = lane & 3;
    const int m0 = blockIdx.y * 128;

    float acc[8][4];
#pragma unroll
    for (int nt = 0; nt < 8; nt++)
        acc[nt][0] = acc[nt][1] = acc[nt][2] = acc[nt][3] = 0.0f;

    for (int k0 = 0; k0 < CDIM; k0 += 32) {
#pragma unroll
        for (int t = 0; t < 16; t++) {
            int e = tid + t * 256; int r = e >> 5, c = e & 31;
            float f = X[(size_t)(m0 + r) * CDIM + k0 + c];
            float h = cvt_tf32f(f);
            Xh[r][c] = h; Xl[r][c] = cvt_tf32f(f - h);
        }
#pragma unroll
        for (int t = 0; t < 8; t++) {
            int e = tid + t * 256; int r = e >> 6, c = e & 63;
            float f = (c < 32) ? Wa[(size_t)(k0 + r) * DDIM + c]
                               : Wb[(size_t)(k0 + r) * DDIM + (c - 32)];
            float h = cvt_tf32f(f);
            Wh[r][c] = h; Wl[r][c] = cvt_tf32f(f - h);
        }
        __syncthreads();

        const int r = w * 16 + qr;
#pragma unroll
        for (int kt = 0; kt < 4; kt++) {
            unsigned ah0 = fasu(Xh[r][kt * 8 + qc]);
            unsigned ah1 = fasu(Xh[r + 8][kt * 8 + qc]);
            unsigned ah2 = fasu(Xh[r][kt * 8 + qc + 4]);
            unsigned ah3 = fasu(Xh[r + 8][kt * 8 + qc + 4]);
            unsigned al0 = fasu(Xl[r][kt * 8 + qc]);
            unsigned al1 = fasu(Xl[r + 8][kt * 8 + qc]);
            unsigned al2 = fasu(Xl[r][kt * 8 + qc + 4]);
            unsigned al3 = fasu(Xl[r + 8][kt * 8 + qc + 4]);
#pragma unroll
            for (int nt = 0; nt < 8; nt++) {
                unsigned bh0 = fasu(Wh[kt * 8 + qc][nt * 8 + qr]);
                unsigned bh1 = fasu(Wh[kt * 8 + qc + 4][nt * 8 + qr]);
                unsigned bl0 = fasu(Wl[kt * 8 + qc][nt * 8 + qr]);
                unsigned bl1 = fasu(Wl[kt * 8 + qc + 4][nt * 8 + qr]);
                mma_tf32(acc[nt], ah0, ah1, ah2, ah3, bh0, bh1);
                mma_tf32(acc[nt], al0, al1, al2, al3, bh0, bh1);
                mma_tf32(acc[nt], ah0, ah1, ah2, ah3, bl0, bl1);
            }
        }
        __syncthreads();
    }

    const int r = m0 + w * 16 + qr;
#pragma unroll
    for (int nt = 0; nt < 8; nt++) {
        if ((nt >> 2) != khalf) {
            int c = nt * 8 + 2 * qc;
            *(float2*)&Y[(size_t)r * 64 + c]       = make_float2(acc[nt][0], acc[nt][1]);
            *(float2*)&Y[(size_t)(r + 8) * 64 + c] = make_float2(acc[nt][2], acc[nt][3]);
        } else {
            int c = (nt - 4 * khalf) * 8 + 2 * qc;
            unsigned hi0, lo0, hi1, lo1;
            split2(acc[nt][0], acc[nt][1], hi0, lo0);
            split2(acc[nt][2], acc[nt][3], hi1, lo1);
            *(unsigned*)&Khi[(size_t)r * 32 + c]       = hi0;
            *(unsigned*)&Klo[(size_t)r * 32 + c]       = lo0;
            *(unsigned*)&Khi[(size_t)(r + 8) * 32 + c] = hi1;
            *(unsigned*)&Klo[(size_t)(r + 8) * 32 + c] = lo1;
        }
    }
}

// ---------------------------------------------------------------------------
// V projection: R2's measured tf32 body (38.8us/GEMM, regs=64), plain args.
// Only change from R2: fp16 (half2) output stores.
// ---------------------------------------------------------------------------
__global__ __launch_bounds__(256, 3)
void proj_v(const float* __restrict__ X, const float* __restrict__ W,
            __half* __restrict__ Y, const float* __restrict__ gate) {
    if (gate && gate[0] == 0.0f) return;

    __shared__ float Xs[128][36];        // pitch 36 -> conflict-free A-frag reads
    __shared__ float Ws[32][72];         // pitch % 32 == 8 -> conflict-free B-frag reads

    const int tid = threadIdx.x, w = tid >> 5, lane = tid & 31;
    const int qr = lane >> 2, qc = lane & 3;
    const int m0 = blockIdx.y * 128, n0 = blockIdx.x * 64;

    float acc[8][4];
#pragma unroll
    for (int nt = 0; nt < 8; nt++)
        acc[nt][0] = acc[nt][1] = acc[nt][2] = acc[nt][3] = 0.0f;

    for (int k0 = 0; k0 < CDIM; k0 += 32) {
#pragma unroll
        for (int t = 0; t < 16; t++) {
            int e = tid + t * 256; int r = e >> 5, c = e & 31;
            Xs[r][c] = cvt_tf32f(X[(size_t)(m0 + r) * CDIM + k0 + c]);
        }
#pragma unroll
        for (int t = 0; t < 8; t++) {
            int e = tid + t * 256; int r = e >> 6, c = e & 63;
            Ws[r][c] = cvt_tf32f(W[(size_t)(k0 + r) * CDIM + n0 + c]);
        }
        __syncthreads();

        const int r = w * 16 + qr;
#pragma unroll
        for (int kt = 0; kt < 4; kt++) {
            unsigned a0 = fasu(Xs[r][kt * 8 + qc]);
            unsigned a1 = fasu(Xs[r + 8][kt * 8 + qc]);
            unsigned a2 = fasu(Xs[r][kt * 8 + qc + 4]);
            unsigned a3 = fasu(Xs[r + 8][kt * 8 + qc + 4]);
#pragma unroll
            for (int nt = 0; nt < 8; nt++) {
                unsigned b0 = fasu(Ws[kt * 8 + qc][nt * 8 + qr]);
                unsigned b1 = fasu(Ws[kt * 8 + qc + 4][nt * 8 + qr]);
                mma_tf32(acc[nt], a0, a1, a2, a3, b0, b1);
            }
        }
        __syncthreads();
    }

    const int r = m0 + w * 16 + qr;
#pragma unroll
    for (int nt = 0; nt < 8; nt++) {
        int c = n0 + nt * 8 + 2 * qc;
        *(__half2*)&Y[(size_t)r * CDIM + c]       = __floats2half2_rn(acc[nt][0], acc[nt][1]);
        *(__half2*)&Y[(size_t)(r + 8) * CDIM + c] = __floats2half2_rn(acc[nt][2], acc[nt][3]);
    }
}

// ---------------------------------------------------------------------------
// Flash attention, fp16 mma, P-in-registers, cp.async double buffer.
// K comes in pre-split fp16 hi/lo; all frags via ldmatrix. 2 blocks/SM.
// (Exact R8 379us body.)
// ---------------------------------------------------------------------------
struct AttnArgs {
    const float*  Q[2];
    const __half* Khi[2];
    const __half* Klo[2];
    const __half* V[2];
};

struct ASmem {
    __half Khi[2][64][40];    // 80B pitch, conflict-free ldmatrix
    __half Klo[2][64][40];
    __half Vs[2][64][264];    // 528B pitch, conflict-free ldmatrix.trans
};
extern __shared__ char attn_raw[];

__global__ __launch_bounds__(256, 2)
void attn16(AttnArgs args, float* __restrict__ out,
            const float* __restrict__ gate, int addMode, int chan0) {
    if (gate && gate[0] == 0.0f) return;
    const float gv = gate ? gate[0] : 1.0f;

    ASmem* S = reinterpret_cast<ASmem*>(attn_raw);
    const int tid = threadIdx.x, w = tid >> 5, lane = tid & 31;
    const int qr = lane >> 2, qc = lane & 3;
    const int wr = w >> 1, wc = w & 1;
    const int qt = blockIdx.x, b = blockIdx.y, z = blockIdx.z;
    const int r0 = wr * 16 + qr;
    const int c0 = wc * 128;

    const size_t rowbase = (size_t)b * LSEQ + (size_t)qt * 64;
    const float*  Qp  = args.Q[z]   + rowbase * 64;
    const __half* Khp = args.Khi[z] + (size_t)b * LSEQ * 32;
    const __half* Klp = args.Klo[z] + (size_t)b * LSEQ * 32;
    const __half* Vp  = args.V[z]   + (size_t)b * LSEQ * CDIM;
    const float isc = rsqrtf((float)DDIM);

    // Q fragments fp32 -> hi/lo fp16
    unsigned qh[2][4], ql[2][4];
#pragma unroll
    for (int kt = 0; kt < 2; kt++) {
        float2 fa = *(const float2*)&Qp[(size_t)r0 * 64 + kt * 16 + 2 * qc];
        float2 fb = *(const float2*)&Qp[(size_t)(r0 + 8) * 64 + kt * 16 + 2 * qc];
        float2 fc = *(const float2*)&Qp[(size_t)r0 * 64 + kt * 16 + 2 * qc + 8];
        float2 fd = *(const float2*)&Qp[(size_t)(r0 + 8) * 64 + kt * 16 + 2 * qc + 8];
        split2(fa.x * isc, fa.y * isc, qh[kt][0], ql[kt][0]);
        split2(fb.x * isc, fb.y * isc, qh[kt][1], ql[kt][1]);
        split2(fc.x * isc, fc.y * isc, qh[kt][2], ql[kt][2]);
        split2(fd.x * isc, fd.y * isc, qh[kt][3], ql[kt][3]);
    }

    float acc[16][4];
#pragma unroll
    for (int nt = 0; nt < 16; nt++)
        acc[nt][0] = acc[nt][1] = acc[nt][2] = acc[nt][3] = 0.0f;
    float m0v = -3.402823466e38f, m1v = -3.402823466e38f, l0 = 0.0f, l1 = 0.0f;

    auto issue = [&](int t) {
        int bufi = t & 1;
        int j0 = t * 64;
        const __half* Vg = Vp + (size_t)j0 * CDIM;
#pragma unroll
        for (int i = 0; i < 8; i++) {
            int e = tid + i * 256; int key = e >> 5, c = e & 31;
            CP16(su(&S->Vs[bufi][key][c * 8]), Vg + (size_t)key * CDIM + c * 8);
        }
#pragma unroll
        for (int i = 0; i < 2; i++) {
            int e = tid + i * 256; int key = e >> 3, c = e & 7;
            if (c < 4)
                CP16(su(&S->Khi[bufi][key][c * 8]),
                     Khp + (size_t)(j0 + key) * 32 + c * 8);
            else
                CP16(su(&S->Klo[bufi][key][(c - 4) * 8]),
                     Klp + (size_t)(j0 + key) * 32 + (c - 4) * 8);
        }
        CP_COMMIT();
    };

    issue(0);
    issue(1);

    for (int t = 0; t < NTILES; t++) {
        const int bufi = t & 1;
        if (t + 1 < NTILES) asm volatile("cp.async.wait_group 1;");
        else                asm volatile("cp.async.wait_group 0;");
        __syncthreads();

        // ---- S = Q K^T, split-fp16 3-mma; K frags via ldmatrix.x4
        float sf[8][4];
#pragma unroll
        for (int nt = 0; nt < 8; nt++)
            sf[nt][0] = sf[nt][1] = sf[nt][2] = sf[nt][3] = 0.0f;
#pragma unroll
        for (int kt = 0; kt < 2; kt++) {
#pragma unroll
            for (int ng = 0; ng < 4; ng++) {
                int krow = ng * 16 + (lane & 7) + ((lane >> 4) << 3);
                int dcol = kt * 16 + ((lane >> 3) & 1) * 8;
                unsigned bh0, bh1, bh2, bh3, bl0, bl1, bl2, bl3;
                LDSM_X4(bh0, bh1, bh2, bh3, su(&S->Khi[bufi][krow][dcol]));
                LDSM_X4(bl0, bl1, bl2, bl3, su(&S->Klo[bufi][krow][dcol]));
                mma16(sf[2 * ng],     qh[kt], bh0, bh1);
                mma16(sf[2 * ng],     ql[kt], bh0, bh1);
                mma16(sf[2 * ng],     qh[kt], bl0, bl1);
                mma16(sf[2 * ng + 1], qh[kt], bh2, bh3);
                mma16(sf[2 * ng + 1], ql[kt], bh2, bh3);
                mma16(sf[2 * ng + 1], qh[kt], bl2, bl3);
            }
        }

        // ---- online softmax (registers + quad shuffles)
        float rm0 = -3.402823466e38f, rm1 = -3.402823466e38f;
#pragma unroll
        for (int nt = 0; nt < 8; nt++) {
            rm0 = fmaxf(rm0, fmaxf(sf[nt][0], sf[nt][1]));
            rm1 = fmaxf(rm1, fmaxf(sf[nt][2], sf[nt][3]));
        }
        rm0 = fmaxf(rm0, __shfl_xor_sync(0xffffffffu, rm0, 1));
        rm0 = fmaxf(rm0, __shfl_xor_sync(0xffffffffu, rm0, 2));
        rm1 = fmaxf(rm1, __shfl_xor_sync(0xffffffffu, rm1, 1));
        rm1 = fmaxf(rm1, __shfl_xor_sync(0xffffffffu, rm1, 2));
        float nm0 = fmaxf(m0v, rm0), nm1 = fmaxf(m1v, rm1);
        float sc0 = __expf(m0v - nm0), sc1 = __expf(m1v - nm1);
        float rs0 = 0.0f, rs1 = 0.0f;
#pragma unroll
        for (int nt = 0; nt < 8; nt++) {
            sf[nt][0] = __expf(sf[nt][0] - nm0); sf[nt][1] = __expf(sf[nt][1] - nm0);
            sf[nt][2] = __expf(sf[nt][2] - nm1); sf[nt][3] = __expf(sf[nt][3] - nm1);
            rs0 += sf[nt][0] + sf[nt][1];
            rs1 += sf[nt][2] + sf[nt][3];
        }
        rs0 += __shfl_xor_sync(0xffffffffu, rs0, 1);
        rs0 += __shfl_xor_sync(0xffffffffu, rs0, 2);
        rs1 += __shfl_xor_sync(0xffffffffu, rs1, 1);
        rs1 += __shfl_xor_sync(0xffffffffu, rs1, 2);
        l0 = l0 * sc0 + rs0; l1 = l1 * sc1 + rs1;
        m0v = nm0; m1v = nm1;
        if (sc0 != 1.0f || sc1 != 1.0f) {
#pragma unroll
            for (int nt = 0; nt < 16; nt++) {
                acc[nt][0] *= sc0; acc[nt][1] *= sc0;
                acc[nt][2] *= sc1; acc[nt][3] *= sc1;
            }
        }

        // ---- pack P into A-fragments (S-frag layout == A-frag layout)
        unsigned pa[4][4];
#pragma unroll
        for (int kt = 0; kt < 4; kt++) {
            pa[kt][0] = h2u(__floats2half2_rn(sf[2 * kt][0],     sf[2 * kt][1]));
            pa[kt][1] = h2u(__floats2half2_rn(sf[2 * kt][2],     sf[2 * kt][3]));
            pa[kt][2] = h2u(__floats2half2_rn(sf[2 * kt + 1][0], sf[2 * kt + 1][1]));
            pa[kt][3] = h2u(__floats2half2_rn(sf[2 * kt + 1][2], sf[2 * kt + 1][3]));
        }

        // ---- acc += P V  (ldmatrix.x4.trans for V B-fragments)
#pragma unroll
        for (int kt = 0; kt < 4; kt++) {
#pragma unroll
            for (int np = 0; np < 8; np++) {
                unsigned b0, b1, b2, b3;
                unsigned addr = su(&S->Vs[bufi][kt * 16 + (lane & 15)]
                                         [c0 + np * 16 + (lane >> 4) * 8]);
                LDSM_X4T(b0, b1, b2, b3, addr);
                mma16(acc[2 * np],     pa[kt], b0, b1);
                mma16(acc[2 * np + 1], pa[kt], b2, b3);
            }
        }

        __syncthreads();
        if (t + 2 < NTILES) issue(t + 2);
    }

    // ---- epilogue
    float il0 = 1.0f / l0, il1 = 1.0f / l1;
    float* o0 = out + (rowbase + r0) * (2 * CDIM) + chan0 + z * CDIM + c0;
    float* o1 = o0 + (size_t)8 * (2 * CDIM);
    if (addMode) {
#pragma unroll
        for (int nt = 0; nt < 16; nt++) {
            int c = nt * 8 + 2 * qc;
            o0[c]     += gv * acc[nt][0] * il0;
            o0[c + 1] += gv * acc[nt][1] * il0;
            o1[c]     += gv * acc[nt][2] * il1;
            o1[c + 1] += gv * acc[nt][3] * il1;
        }
    } else {
#pragma unroll
        for (int nt = 0; nt < 16; nt++) {
            int c = nt * 8 + 2 * qc;
            *(float2*)&o0[c] = make_float2(acc[nt][0] * il0, acc[nt][1] * il0);
            *(float2*)&o1[c] = make_float2(acc[nt][2] * il1, acc[nt][3] * il1);
        }
    }
}

// ---------------------------------------------------------------------------
// Launcher — exact R8 (379us) structure: plain args, 12 launches.
// ---------------------------------------------------------------------------
extern "C" void kernel_launch(void* const* d_in, const int* in_sizes, int n_in,
                              void* d_out, int out_size) {
    const float* x = (const float*)d_in[0];
    const float* w[13];
    for (int i = 1; i <= 12; i++) w[i] = (const float*)d_in[i];
    const float* alpha = (const float*)d_in[13];
    const float* gamma = (const float*)d_in[14];
    float* out = (float*)d_out;

    float *ecg, *pcg, *qk; __half *vh, *khi, *klo;
    cudaGetSymbolAddress((void**)&ecg, g_ecg);
    cudaGetSymbolAddress((void**)&pcg, g_pcg);
    cudaGetSymbolAddress((void**)&qk,  g_QK);
    cudaGetSymbolAddress((void**)&vh,  g_Vh);
    cudaGetSymbolAddress((void**)&khi, g_Khi);
    cudaGetSymbolAddress((void**)&klo, g_Klo);

    auto QK = [&](int a) { return qk  + (size_t)a * MROWS * 64; };
    auto KH = [&](int a) { return khi + (size_t)a * MROWS * 32; };
    auto KL = [&](int a) { return klo + (size_t)a * MROWS * 32; };
    auto VH = [&](int a) { return vh  + (size_t)a * MROWS * CDIM; };

    cudaFuncSetAttribute(attn16, cudaFuncAttributeMaxDynamicSharedMemorySize,
                         (int)sizeof(ASmem));

    // 1) de-interleave
    split_kernel<<<(MROWS * CDIM + 255) / 256, 256>>>((const float2*)x, ecg, pcg);

    // 2) projections
    dim3 gQ(1, MROWS / 128);
    dim3 gV(CDIM / 64, MROWS / 128);
    // QK(0) = ecg@[w4|w11] = [Q0 | K1] -> K half 1 feeds attn z=1
    proj_qk3<<<gQ, 256>>>(ecg, w[4], w[11], QK(0), KH(1), KL(1), 1, nullptr);
    // QK(1) = pcg@[w5|w10] = [K0 | Q1] -> K half 0 feeds attn z=0
    proj_qk3<<<gQ, 256>>>(pcg, w[5], w[10], QK(1), KH(0), KL(0), 0, nullptr);
    // intra:  [Q2|K2], [Q3|K3] -> K half 1
    proj_qk3<<<gQ, 256>>>(ecg, w[1], w[2],  QK(2), KH(2), KL(2), 1, alpha);
    proj_qk3<<<gQ, 256>>>(pcg, w[7], w[8],  QK(3), KH(3), KL(3), 1, gamma);
    // V projections (tf32 mma, fp16 out)
    proj_v<<<gV, 256>>>(pcg, w[6],  VH(0), nullptr);
    proj_v<<<gV, 256>>>(ecg, w[12], VH(1), nullptr);
    proj_v<<<gV, 256>>>(ecg, w[3],  VH(2), alpha);
    proj_v<<<gV, 256>>>(pcg, w[9],  VH(3), gamma);

    // 3) attention: both ungated paths in one launch (z = 0,1)
    size_t smem = sizeof(ASmem);
    AttnArgs ap{};
    ap.Q[0] = QK(0);      ap.Khi[0] = KH(0); ap.Klo[0] = KL(0); ap.V[0] = VH(0);
    ap.Q[1] = QK(1) + 32; ap.Khi[1] = KH(1); ap.Klo[1] = KL(1); ap.V[1] = VH(1);
    attn16<<<dim3(LSEQ / 64, NBATCH, 2), 256, smem>>>(ap, out, nullptr, 0, 0);

    // gated intra paths
    AttnArgs a2{};
    a2.Q[0] = QK(2); a2.Khi[0] = KH(2); a2.Klo[0] = KL(2); a2.V[0] = VH(2);
    attn16<<<dim3(LSEQ / 64, NBATCH, 1), 256, smem>>>(a2, out, alpha, 1, 0);
    AttnArgs a3{};
    a3.Q[0] = QK(3); a3.Khi[0] = KH(3); a3.Klo[0] = KL(3); a3.V[0] = VH(3);
    attn16<<<dim3(LSEQ / 64, NBATCH, 1), 256, smem>>>(a3, out, gamma, 1, CDIM);
}